// round 13
// baseline (speedup 1.0000x reference)
#include <cuda_runtime.h>
#include <cuda_fp16.h>

#define BB  2
#define SS  2048
#define DD  1024
#define HH  1024
#define NHH 16
#define DHH 64

// score prescale: 1/8 (dh=64) folded with log2(e) for exp2-domain softmax
#define SC_PRE 0.180336880f

// ---------------------------------------------------------------------------
// Static scratch
// ---------------------------------------------------------------------------
__device__ __half g_A16[3][BB * SS * DD];          // fp16 KEY, QUERY, VALUE
__device__ __half g_W16[4][HH * DD];               // fp16 Wk, Wq, Wv, Wo
__device__ __half g_Kh[BB * NHH * SS * DHH];       // head-split projections
__device__ __half g_Qh[BB * NHH * SS * DHH];
__device__ __half g_Vh[BB * NHH * SS * DHH];
__device__ __half g_Xt[BB * HH * SS];              // X transposed [b][c][s]

// ---------------------------------------------------------------------------
// PTX helpers
// ---------------------------------------------------------------------------
__device__ __forceinline__ unsigned sptr(const void* p) {
    unsigned a;
    asm("{.reg .u64 t; cvta.to.shared.u64 t, %1; cvt.u32.u64 %0, t;}" : "=r"(a) : "l"(p));
    return a;
}
__device__ __forceinline__ void ldsm4(unsigned& r0, unsigned& r1, unsigned& r2, unsigned& r3, unsigned a) {
    asm volatile("ldmatrix.sync.aligned.m8n8.x4.shared.b16 {%0,%1,%2,%3},[%4];\n"
                 : "=r"(r0), "=r"(r1), "=r"(r2), "=r"(r3) : "r"(a));
}
__device__ __forceinline__ void ldsm4t(unsigned& r0, unsigned& r1, unsigned& r2, unsigned& r3, unsigned a) {
    asm volatile("ldmatrix.sync.aligned.m8n8.x4.trans.shared.b16 {%0,%1,%2,%3},[%4];\n"
                 : "=r"(r0), "=r"(r1), "=r"(r2), "=r"(r3) : "r"(a));
}
__device__ __forceinline__ void mma16816(float* c, unsigned a0, unsigned a1, unsigned a2, unsigned a3,
                                         unsigned b0, unsigned b1) {
    asm volatile("mma.sync.aligned.m16n8k16.row.col.f32.f16.f16.f32 "
                 "{%0,%1,%2,%3},{%4,%5,%6,%7},{%8,%9},{%0,%1,%2,%3};\n"
                 : "+f"(c[0]), "+f"(c[1]), "+f"(c[2]), "+f"(c[3])
                 : "r"(a0), "r"(a1), "r"(a2), "r"(a3), "r"(b0), "r"(b1));
}
__device__ __forceinline__ void cpa16(unsigned d, const void* s) {
    asm volatile("cp.async.cg.shared.global [%0],[%1],16;\n" :: "r"(d), "l"(s));
}
__device__ __forceinline__ void cpa_commit() { asm volatile("cp.async.commit_group;\n"); }
template <int N> __device__ __forceinline__ void cpa_wait() {
    asm volatile("cp.async.wait_group %0;\n" :: "n"(N));
}

// ---------------------------------------------------------------------------
// Fused fp32->fp16 conversion, 2 float4 per thread.
// ---------------------------------------------------------------------------
#define IN4 (BB * SS * DD / 4)
#define W4  (HH * DD / 4)
#define TOT4 (3 * IN4 + 4 * W4)
__global__ void __launch_bounds__(256) cvt_all(const float4* __restrict__ k,
                                               const float4* __restrict__ q,
                                               const float4* __restrict__ v,
                                               const float4* __restrict__ wk,
                                               const float4* __restrict__ wq,
                                               const float4* __restrict__ wv,
                                               const float4* __restrict__ wo)
{
#pragma unroll
    for (int e = 0; e < 2; e++) {
        int idx = (blockIdx.x * 2 + e) * 256 + threadIdx.x;
        const float4* src;
        __half2* dst;
        int li;
        if (idx < 3 * IN4) {
            int which = idx / IN4;
            li = idx - which * IN4;
            src = (which == 0) ? k : (which == 1) ? q : v;
            dst = (__half2*)g_A16[which];
        } else {
            int r = idx - 3 * IN4;
            int which = r / W4;
            li = r - which * W4;
            src = (which == 0) ? wk : (which == 1) ? wq : (which == 2) ? wv : wo;
            dst = (__half2*)g_W16[which];
        }
        float4 val = src[li];
        dst[li * 2]     = __floats2half2_rn(val.x, val.y);
        dst[li * 2 + 1] = __floats2half2_rn(val.z, val.w);
    }
}

// ---------------------------------------------------------------------------
// Fused projection GEMM (K, Q, V; which = blockIdx.z). BM=128 BN=128 BK=32.
// ---------------------------------------------------------------------------
__global__ void __launch_bounds__(256) proj_fused(const float* __restrict__ bk,
                                                  const float* __restrict__ bq,
                                                  const float* __restrict__ bv) {
    const int which = blockIdx.z;
    const __half* A = g_A16[which];
    const __half* W = g_W16[which];
    __half* out = (which == 0) ? g_Kh : (which == 1) ? g_Qh : g_Vh;
    const float* bias = (which == 0) ? bk : (which == 1) ? bq : bv;

    __shared__ union {
        __half t[3][2][128][40];
        __half C[128][136];
    } sh;

    const int tid = threadIdx.x;
    const int bm = blockIdx.y * 128, bn = blockIdx.x * 128;
    const int w = tid >> 5, l = tid & 31;
    const int wm = w >> 2, wn = w & 3;

    const int c0 = tid, c1 = tid + 256;
    const int ar0 = c0 >> 2, as0 = (c0 & 3) * 8;
    const int ar1 = c1 >> 2, as1 = (c1 & 3) * 8;

    const unsigned sBase = sptr(&sh.t[0][0][0][0]);
    const unsigned stgStride = 2 * 128 * 40 * 2;
    const unsigned bOff = 128 * 40 * 2;

    auto issue = [&](int kb, int st) {
        const __half* Ag = A + (size_t)bm * DD + kb * 32;
        const __half* Bg = W + (size_t)bn * DD + kb * 32;
        unsigned s = sBase + st * stgStride;
        cpa16(s + (unsigned)(ar0 * 40 + as0) * 2, Ag + (size_t)ar0 * DD + as0);
        cpa16(s + (unsigned)(ar1 * 40 + as1) * 2, Ag + (size_t)ar1 * DD + as1);
        cpa16(s + bOff + (unsigned)(ar0 * 40 + as0) * 2, Bg + (size_t)ar0 * DD + as0);
        cpa16(s + bOff + (unsigned)(ar1 * 40 + as1) * 2, Bg + (size_t)ar1 * DD + as1);
        cpa_commit();
    };

    float acc[4][4][4];
#pragma unroll
    for (int mt = 0; mt < 4; mt++)
#pragma unroll
        for (int nt = 0; nt < 4; nt++)
#pragma unroll
            for (int r = 0; r < 4; r++) acc[mt][nt][r] = 0.f;

    const int a_r = l & 15, a_c = (l >> 4) * 8;
    const int b_r = (l & 7) | ((l >> 1) & 8), b_c = l & 8;

    issue(0, 0);
    issue(1, 1);

    const int NKB = DD / 32;
    for (int kb = 0; kb < NKB; kb++) {
        const int st = kb % 3;
        if (kb == NKB - 1) cpa_wait<0>(); else cpa_wait<1>();
        __syncthreads();
        if (kb + 2 < NKB) issue(kb + 2, (kb + 2) % 3);

        const unsigned sA = sBase + st * stgStride;
        const unsigned sB = sA + bOff;
#pragma unroll
        for (int ks = 0; ks < 2; ks++) {
            unsigned a[4][4], bfr[2][4];
#pragma unroll
            for (int mt = 0; mt < 4; mt++) {
                int r = wm * 64 + mt * 16 + a_r;
                int c = ks * 16 + a_c;
                ldsm4(a[mt][0], a[mt][1], a[mt][2], a[mt][3],
                      sA + (unsigned)(r * 40 + c) * 2);
            }
#pragma unroll
            for (int np = 0; np < 2; np++) {
                int r = wn * 32 + np * 16 + b_r;
                int c = ks * 16 + b_c;
                ldsm4(bfr[np][0], bfr[np][1], bfr[np][2], bfr[np][3],
                      sB + (unsigned)(r * 40 + c) * 2);
            }
#pragma unroll
            for (int mt = 0; mt < 4; mt++)
#pragma unroll
                for (int nt = 0; nt < 4; nt++)
                    mma16816(acc[mt][nt], a[mt][0], a[mt][1], a[mt][2], a[mt][3],
                             bfr[nt >> 1][(nt & 1) * 2], bfr[nt >> 1][(nt & 1) * 2 + 1]);
        }
    }
    __syncthreads();

#pragma unroll
    for (int nt = 0; nt < 4; nt++) {
        int c0v = wn * 32 + nt * 8 + 2 * (l & 3);
        float bv0 = bias[bn + c0v], bv1 = bias[bn + c0v + 1];
#pragma unroll
        for (int mt = 0; mt < 4; mt++) {
            int r0 = wm * 64 + mt * 16 + (l >> 2);
            *(__half2*)&sh.C[r0][c0v]     = __floats2half2_rn(acc[mt][nt][0] + bv0, acc[mt][nt][1] + bv1);
            *(__half2*)&sh.C[r0 + 8][c0v] = __floats2half2_rn(acc[mt][nt][2] + bv0, acc[mt][nt][3] + bv1);
        }
    }
    __syncthreads();

    const int h = tid & 15, sg = tid >> 4;
#pragma unroll
    for (int sl = 0; sl < 8; sl++) {
        int s = sg * 8 + sl;
        int m = bm + s;
        int b_ = m >> 11, sloc = m & 2047;
        __half tmp[8];
#pragma unroll
        for (int dd = 0; dd < 8; dd++) tmp[dd] = sh.C[s][h + 16 * dd];
        *(uint4*)&out[(((size_t)(b_ * NHH + h)) * SS + sloc) * DHH + (bn >> 4)] = *(uint4*)tmp;
    }
}

// ---------------------------------------------------------------------------
// FULLY FUSED attention v5: Q in registers; softmax fused into next score
// phase; scores stored pre-scaled into exp2 domain; softmax uses half2
// loads/stores (256 active threads) + exp2f (bare MUFU.EX2).
// smem layout identical to v4: V ring 2x18432 | K ring 2x18432 | S 2x12288.
// ---------------------------------------------------------------------------
#define ICH 16
#define NIT (SS / ICH)
__global__ void __launch_bounds__(512, 1) attn_fused() {
    extern __shared__ __half sm[];
    __half* QV = sm;                        // Q (prologue) -> V ring 2x18432
    __half* Ss = sm + 36864 + 2 * 18432;    // S ring 2 x 12288

    const int b = blockIdx.y;
    const int kbase = blockIdx.x * 32;
    const int tid = threadIdx.x;
    const int h = tid >> 5;                 // warp = head
    const int l = tid & 31;

    const unsigned sQV = sptr(QV);
    const unsigned sK = sQV + 36864u * 2;   // K ring base (bytes)
    const unsigned sS = sK + 2u * 18432 * 2;
    const unsigned Vbs = 18432 * 2;
    const unsigned Kbs = 18432 * 2;
    const unsigned Sbs = 12288 * 2;

    const int a_r = l & 15, a_c = (l >> 4) * 8;
    const int b_r = (l & 7) | ((l >> 1) & 8), b_c = l & 8;
    const int bt_r = (l & 7) + ((l >> 3) & 1) * 8;
    const int bt_c = ((l >> 4) & 1) * 8;

    const __half* Kg = g_Kh + (size_t)(b * NHH) * SS * DHH;
    const __half* Qg = g_Qh + (size_t)(b * NHH) * SS * DHH;
    const __half* Vg = g_Vh + (size_t)(b * NHH) * SS * DHH;

    auto loadChunk = [&](const __half* src, unsigned dstbase, int ig0) {
#pragma unroll
        for (int t = 0; t < 4; t++) {
            int id = tid + t * 512;
            int row = id >> 3;
            int seg = (id & 7) * 8;
            int h2 = row >> 4, il = row & 15;
            cpa16(dstbase + (unsigned)(row * 72 + seg) * 2,
                  src + ((size_t)h2 * SS + ig0 + il) * DHH + seg);
        }
        cpa_commit();
    };

    // ---- prologue: Q (group), K[0] (group), K[1] (group) ----
#pragma unroll
    for (int t = 0; t < 8; t++) {
        int id = tid + t * 512;
        int row = id >> 3;
        int seg = (id & 7) * 8;
        int h2 = row >> 5, kl = row & 31;
        cpa16(sQV + (unsigned)(row * 72 + seg) * 2,
              Qg + ((size_t)h2 * SS + kbase + kl) * DHH + seg);
    }
    cpa_commit();
    loadChunk(Kg, sK, 0);
    loadChunk(Kg, sK + Kbs, ICH);
    cpa_wait<2>();                 // Q done
    __syncthreads();

    // ---- Q -> registers ----
    unsigned aq[2][4][4];
#pragma unroll
    for (int mt = 0; mt < 2; mt++)
#pragma unroll
        for (int ks = 0; ks < 4; ks++)
            ldsm4(aq[mt][ks][0], aq[mt][ks][1], aq[mt][ks][2], aq[mt][ks][3],
                  sQV + (unsigned)((h * 32 + mt * 16 + a_r) * 72 + ks * 16 + a_c) * 2);
    __syncthreads();               // QV region becomes V ring

    float oacc[2][8][4];
#pragma unroll
    for (int mt = 0; mt < 2; mt++)
#pragma unroll
        for (int nt = 0; nt < 8; nt++)
#pragma unroll
            for (int r = 0; r < 4; r++) oacc[mt][nt][r] = 0.f;

    for (int c = 0; c <= NIT; c++) {
        // ---- A-top: wait + barrier, then issue V[c] ----
        if (c < NIT - 1) cpa_wait<1>(); else cpa_wait<0>();
        __syncthreads();
        if (c < NIT) loadChunk(Vg, sQV + (unsigned)(c & 1) * Vbs, c * ICH);

        // ---- A-body: softmax[c-1] (half2 + exp2) fused with score[c] ----
        if (c >= 1 && tid < 256) {
            __half* Sp = Ss + ((c - 1) & 1) * 12288;
            int kq = tid >> 3, ix = (tid & 7) * 2;   // 32 k x 8 i-pairs
            float2 v[NHH];
            float mx = -1e30f;
#pragma unroll
            for (int h2 = 0; h2 < NHH; h2++) {
                v[h2] = __half22float2(*(__half2*)&Sp[(h2 * 32 + kq) * 24 + ix]);
                mx = fmaxf(mx, fmaxf(v[h2].x, v[h2].y));
            }
            float sx = 0.f, sy = 0.f;
#pragma unroll
            for (int h2 = 0; h2 < NHH; h2++) {
                v[h2].x = exp2f(v[h2].x - mx);
                v[h2].y = exp2f(v[h2].y - mx);
                sx += v[h2].x;
                sy += v[h2].y;
            }
            float ivx = 1.f / sx, ivy = 1.f / sy;
#pragma unroll
            for (int h2 = 0; h2 < NHH; h2++)
                *(__half2*)&Sp[(h2 * 32 + kq) * 24 + ix] =
                    __floats2half2_rn(v[h2].x * ivx, v[h2].y * ivy);
        }
        if (c < NIT) {
            float sacc[2][2][4];
#pragma unroll
            for (int mt = 0; mt < 2; mt++)
#pragma unroll
                for (int nt = 0; nt < 2; nt++)
#pragma unroll
                    for (int r = 0; r < 4; r++) sacc[mt][nt][r] = 0.f;

            const unsigned kcur = sK + (unsigned)(c & 1) * Kbs;
#pragma unroll
            for (int ks = 0; ks < 4; ks++) {
                unsigned bk4[4];
                ldsm4(bk4[0], bk4[1], bk4[2], bk4[3],
                      kcur + (unsigned)((h * ICH + b_r) * 72 + ks * 16 + b_c) * 2);
#pragma unroll
                for (int mt = 0; mt < 2; mt++) {
                    mma16816(sacc[mt][0], aq[mt][ks][0], aq[mt][ks][1], aq[mt][ks][2], aq[mt][ks][3],
                             bk4[0], bk4[1]);
                    mma16816(sacc[mt][1], aq[mt][ks][0], aq[mt][ks][1], aq[mt][ks][2], aq[mt][ks][3],
                             bk4[2], bk4[3]);
                }
            }
            __half* Sw = Ss + (c & 1) * 12288;
#pragma unroll
            for (int mt = 0; mt < 2; mt++)
#pragma unroll
                for (int nt = 0; nt < 2; nt++) {
                    int r = mt * 16 + (l >> 2);
                    int cc = nt * 8 + 2 * (l & 3);
                    *(__half2*)&Sw[(h * 32 + r) * 24 + cc] =
                        __floats2half2_rn(sacc[mt][nt][0] * SC_PRE, sacc[mt][nt][1] * SC_PRE);
                    *(__half2*)&Sw[(h * 32 + r + 8) * 24 + cc] =
                        __floats2half2_rn(sacc[mt][nt][2] * SC_PRE, sacc[mt][nt][3] * SC_PRE);
                }
        }
        __syncthreads();   // S_raw[c] + S_norm[c-1] visible

        // ---- B: AV[c-1]; then issue K[c+2] ----
        if (c >= 1) {
            const unsigned svb = sQV + (unsigned)((c - 1) & 1) * Vbs;
            const unsigned ssb = sS + (unsigned)((c - 1) & 1) * Sbs;
            unsigned as[2][4], bv[4][4];
#pragma unroll
            for (int mt = 0; mt < 2; mt++)
                ldsm4(as[mt][0], as[mt][1], as[mt][2], as[mt][3],
                      ssb + (unsigned)((h * 32 + mt * 16 + a_r) * 24 + a_c) * 2);
#pragma unroll
            for (int np = 0; np < 4; np++)
                ldsm4t(bv[np][0], bv[np][1], bv[np][2], bv[np][3],
                       svb + (unsigned)((h * ICH + bt_r) * 72 + np * 16 + bt_c) * 2);
#pragma unroll
            for (int mt = 0; mt < 2; mt++)
#pragma unroll
                for (int nt = 0; nt < 8; nt++)
                    mma16816(oacc[mt][nt], as[mt][0], as[mt][1], as[mt][2], as[mt][3],
                             bv[nt >> 1][(nt & 1) * 2], bv[nt >> 1][(nt & 1) * 2 + 1]);
        }
        if (c + 2 <= NIT - 1) loadChunk(Kg, sK + (unsigned)((c + 2) & 1) * Kbs, (c + 2) * ICH);
    }
    __syncthreads();   // all AV reads done before Osm overwrites QV region

    // ---- epilogue: stage O to smem [ch=16j+h][k stride 40], uint4 writeout --
    __half* Osm = sm;
#pragma unroll
    for (int mt = 0; mt < 2; mt++) {
        int k0 = mt * 16 + (l >> 2);
#pragma unroll
        for (int nt = 0; nt < 8; nt++) {
            int j0 = nt * 8 + 2 * (l & 3);
            Osm[(16 * j0 + h) * 40 + k0]           = __float2half_rn(oacc[mt][nt][0]);
            Osm[(16 * (j0 + 1) + h) * 40 + k0]     = __float2half_rn(oacc[mt][nt][1]);
            Osm[(16 * j0 + h) * 40 + k0 + 8]       = __float2half_rn(oacc[mt][nt][2]);
            Osm[(16 * (j0 + 1) + h) * 40 + k0 + 8] = __float2half_rn(oacc[mt][nt][3]);
        }
    }
    __syncthreads();

    __half* Xb = g_Xt + (size_t)b * HH * SS;
#pragma unroll
    for (int e = 0; e < 8; e++) {
        int id = e * 512 + tid;
        int kseg = (id & 3) * 8;
        int cc = id >> 2;
        uint4 val = *(const uint4*)&Osm[cc * 40 + kseg];
        *(uint4*)&Xb[(size_t)cc * SS + kbase + kseg] = val;
    }
}

// ---------------------------------------------------------------------------
// Output projection: out = X @ Wo^T + bias, 3-stage cp.async.
// ---------------------------------------------------------------------------
__global__ void __launch_bounds__(256) outproj_gemm(const float* __restrict__ bias,
                                                    float* __restrict__ out) {
    const __half* Wo = g_W16[3];

    __shared__ __half At[3][32][72];
    __shared__ __half Bt[3][128][40];

    const int tid = threadIdx.x;
    const int bm = blockIdx.y * 64, bn = blockIdx.x * 128;
    const int b_ = bm >> 11, sbase = bm & 2047;
    const int w = tid >> 5, l = tid & 31;
    const int wm = w >> 2, wn = w & 3;

    const int arow = tid >> 3, aseg = (tid & 7) * 8;
    const int bc0 = tid, bc1 = tid + 256;
    const int br0 = bc0 >> 2, bs0 = (bc0 & 3) * 8;
    const int br1 = bc1 >> 2, bs1 = (bc1 & 3) * 8;

    const int at_r = (l & 7) + ((l >> 4) & 1) * 8;
    const int at_c = ((l >> 3) & 1) * 8;
    const int b_r = (l & 7) | ((l >> 1) & 8), b_c = l & 8;

    const unsigned sAt = sptr(&At[0][0][0]);
    const unsigned sBt = sptr(&Bt[0][0][0]);
    const unsigned Abs = 32 * 72 * 2, Bbs = 128 * 40 * 2;

    const __half* Abase = g_Xt + (size_t)b_ * HH * SS + sbase;

    auto issue = [&](int kb, int st) {
        cpa16(sAt + st * Abs + (unsigned)(arow * 72 + aseg) * 2,
              Abase + (size_t)(kb * 32 + arow) * SS + aseg);
        cpa16(sBt + st * Bbs + (unsigned)(br0 * 40 + bs0) * 2,
              Wo + (size_t)(bn + br0) * HH + kb * 32 + bs0);
        cpa16(sBt + st * Bbs + (unsigned)(br1 * 40 + bs1) * 2,
              Wo + (size_t)(bn + br1) * HH + kb * 32 + bs1);
        cpa_commit();
    };

    float acc[2][4][4];
#pragma unroll
    for (int mt = 0; mt < 2; mt++)
#pragma unroll
        for (int nt = 0; nt < 4; nt++)
#pragma unroll
            for (int r = 0; r < 4; r++) acc[mt][nt][r] = 0.f;

    issue(0, 0);
    issue(1, 1);

    const int NKB = HH / 32;
    for (int kb = 0; kb < NKB; kb++) {
        const int st = kb % 3;
        if (kb == NKB - 1) cpa_wait<0>(); else cpa_wait<1>();
        __syncthreads();
        if (kb + 2 < NKB) issue(kb + 2, (kb + 2) % 3);

#pragma unroll
        for (int ks = 0; ks < 2; ks++) {
            unsigned a[2][4], bfr[2][4];
#pragma unroll
            for (int mt = 0; mt < 2; mt++) {
                int r = ks * 16 + at_r;
                int c = wm * 32 + mt * 16 + at_c;
                ldsm4t(a[mt][0], a[mt][1], a[mt][2], a[mt][3],
                       sAt + st * Abs + (unsigned)(r * 72 + c) * 2);
            }
#pragma unroll
            for (int np = 0; np < 2; np++) {
                int r = wn * 32 + np * 16 + b_r;
                int c = ks * 16 + b_c;
                ldsm4(bfr[np][0], bfr[np][1], bfr[np][2], bfr[np][3],
                      sBt + st * Bbs + (unsigned)(r * 40 + c) * 2);
            }
#pragma unroll
            for (int mt = 0; mt < 2; mt++)
#pragma unroll
                for (int nt = 0; nt < 4; nt++)
                    mma16816(acc[mt][nt], a[mt][0], a[mt][1], a[mt][2], a[mt][3],
                             bfr[nt >> 1][(nt & 1) * 2], bfr[nt >> 1][(nt & 1) * 2 + 1]);
        }
        __syncthreads();
    }

#pragma unroll
    for (int nt = 0; nt < 4; nt++) {
        int c0 = bn + wn * 32 + nt * 8 + 2 * (l & 3);
        float bv0 = bias[c0], bv1 = bias[c0 + 1];
#pragma unroll
        for (int mt = 0; mt < 2; mt++) {
            int r0 = bm + wm * 32 + mt * 16 + (l >> 2);
            float2 v0 = make_float2(acc[mt][nt][0] + bv0, acc[mt][nt][1] + bv1);
            float2 v1 = make_float2(acc[mt][nt][2] + bv0, acc[mt][nt][3] + bv1);
            *(float2*)&out[(size_t)r0 * HH + c0] = v0;
            *(float2*)&out[(size_t)(r0 + 8) * HH + c0] = v1;
        }
    }
}

// ---------------------------------------------------------------------------
// Launch
// ---------------------------------------------------------------------------
extern "C" void kernel_launch(void* const* d_in, const int* in_sizes, int n_in,
                              void* d_out, int out_size)
{
    const float* KEY   = (const float*)d_in[0];
    const float* VALUE = (const float*)d_in[1];
    const float* QUERY = (const float*)d_in[2];
    const float* Wk_w  = (const float*)d_in[3];
    const float* Wk_b  = (const float*)d_in[4];
    const float* Wq_w  = (const float*)d_in[5];
    const float* Wq_b  = (const float*)d_in[6];
    const float* Wv_w  = (const float*)d_in[7];
    const float* Wv_b  = (const float*)d_in[8];
    const float* Wo_w  = (const float*)d_in[9];
    const float* Wo_b  = (const float*)d_in[10];
    float* out = (float*)d_out;

    const int fsm = (36864 + 2 * 18432 + 2 * 12288) * 2;   // 196,608 B
    static bool attr_done = false;
    if (!attr_done) {
        cudaFuncSetAttribute(attn_fused, cudaFuncAttributeMaxDynamicSharedMemorySize, fsm);
        attr_done = true;
    }

    cvt_all<<<TOT4 / 512, 256>>>((const float4*)KEY, (const float4*)QUERY,
                                 (const float4*)VALUE, (const float4*)Wk_w,
                                 (const float4*)Wq_w, (const float4*)Wv_w,
                                 (const float4*)Wo_w);

    dim3 pg(HH / 128, (BB * SS) / 128, 3);         // 768 CTAs
    proj_fused<<<pg, 256>>>(Wk_b, Wq_b, Wv_b);

    dim3 fg(SS / 32, BB);                          // (64, 2) = 128 CTAs
    attn_fused<<<fg, 512, fsm>>>();

    dim3 og(HH / 128, (BB * SS) / 64);             // (8, 64)
    outproj_gemm<<<og, 256>>>(Wo_b, out);
}

// round 15
// speedup vs baseline: 1.0850x; 1.0850x over previous
#include <cuda_runtime.h>
#include <cuda_fp16.h>

#define BB  2
#define SS  2048
#define DD  1024
#define HH  1024
#define NHH 16
#define DHH 64

// ---------------------------------------------------------------------------
// Static scratch
// ---------------------------------------------------------------------------
__device__ __half g_A16[3][BB * SS * DD];          // fp16 KEY, QUERY, VALUE
__device__ __half g_W16[4][HH * DD];               // fp16 Wk, Wq, Wv, Wo
__device__ __half g_Kh[BB * NHH * SS * DHH];       // head-split projections
__device__ __half g_Qh[BB * NHH * SS * DHH];
__device__ __half g_Vh[BB * NHH * SS * DHH];
__device__ __half g_Xt[BB * HH * SS];              // X transposed [b][c][s]

// ---------------------------------------------------------------------------
// PTX helpers
// ---------------------------------------------------------------------------
__device__ __forceinline__ unsigned sptr(const void* p) {
    unsigned a;
    asm("{.reg .u64 t; cvta.to.shared.u64 t, %1; cvt.u32.u64 %0, t;}" : "=r"(a) : "l"(p));
    return a;
}
__device__ __forceinline__ void ldsm4(unsigned& r0, unsigned& r1, unsigned& r2, unsigned& r3, unsigned a) {
    asm volatile("ldmatrix.sync.aligned.m8n8.x4.shared.b16 {%0,%1,%2,%3},[%4];\n"
                 : "=r"(r0), "=r"(r1), "=r"(r2), "=r"(r3) : "r"(a));
}
__device__ __forceinline__ void ldsm4t(unsigned& r0, unsigned& r1, unsigned& r2, unsigned& r3, unsigned a) {
    asm volatile("ldmatrix.sync.aligned.m8n8.x4.trans.shared.b16 {%0,%1,%2,%3},[%4];\n"
                 : "=r"(r0), "=r"(r1), "=r"(r2), "=r"(r3) : "r"(a));
}
__device__ __forceinline__ void mma16816(float* c, unsigned a0, unsigned a1, unsigned a2, unsigned a3,
                                         unsigned b0, unsigned b1) {
    asm volatile("mma.sync.aligned.m16n8k16.row.col.f32.f16.f16.f32 "
                 "{%0,%1,%2,%3},{%4,%5,%6,%7},{%8,%9},{%0,%1,%2,%3};\n"
                 : "+f"(c[0]), "+f"(c[1]), "+f"(c[2]), "+f"(c[3])
                 : "r"(a0), "r"(a1), "r"(a2), "r"(a3), "r"(b0), "r"(b1));
}
__device__ __forceinline__ void cpa16(unsigned d, const void* s) {
    asm volatile("cp.async.cg.shared.global [%0],[%1],16;\n" :: "r"(d), "l"(s));
}
__device__ __forceinline__ void cpa_commit() { asm volatile("cp.async.commit_group;\n"); }
template <int N> __device__ __forceinline__ void cpa_wait() {
    asm volatile("cp.async.wait_group %0;\n" :: "n"(N));
}

// ---------------------------------------------------------------------------
// Fused fp32->fp16 conversion, 2 float4 per thread.
// ---------------------------------------------------------------------------
#define IN4 (BB * SS * DD / 4)
#define W4  (HH * DD / 4)
#define TOT4 (3 * IN4 + 4 * W4)
__global__ void __launch_bounds__(256) cvt_all(const float4* __restrict__ k,
                                               const float4* __restrict__ q,
                                               const float4* __restrict__ v,
                                               const float4* __restrict__ wk,
                                               const float4* __restrict__ wq,
                                               const float4* __restrict__ wv,
                                               const float4* __restrict__ wo)
{
#pragma unroll
    for (int e = 0; e < 2; e++) {
        int idx = (blockIdx.x * 2 + e) * 256 + threadIdx.x;
        const float4* src;
        __half2* dst;
        int li;
        if (idx < 3 * IN4) {
            int which = idx / IN4;
            li = idx - which * IN4;
            src = (which == 0) ? k : (which == 1) ? q : v;
            dst = (__half2*)g_A16[which];
        } else {
            int r = idx - 3 * IN4;
            int which = r / W4;
            li = r - which * W4;
            src = (which == 0) ? wk : (which == 1) ? wq : (which == 2) ? wv : wo;
            dst = (__half2*)g_W16[which];
        }
        float4 val = src[li];
        dst[li * 2]     = __floats2half2_rn(val.x, val.y);
        dst[li * 2 + 1] = __floats2half2_rn(val.z, val.w);
    }
}

// ---------------------------------------------------------------------------
// Fused projection GEMM (K, Q, V; which = blockIdx.z). BM=128 BN=128 BK=32.
// (R12-proven HMMA version.)
// ---------------------------------------------------------------------------
__global__ void __launch_bounds__(256) proj_fused(const float* __restrict__ bk,
                                                  const float* __restrict__ bq,
                                                  const float* __restrict__ bv) {
    const int which = blockIdx.z;
    const __half* A = g_A16[which];
    const __half* W = g_W16[which];
    __half* out = (which == 0) ? g_Kh : (which == 1) ? g_Qh : g_Vh;
    const float* bias = (which == 0) ? bk : (which == 1) ? bq : bv;

    __shared__ union {
        __half t[3][2][128][40];
        __half C[128][136];
    } sh;

    const int tid = threadIdx.x;
    const int bm = blockIdx.y * 128, bn = blockIdx.x * 128;
    const int w = tid >> 5, l = tid & 31;
    const int wm = w >> 2, wn = w & 3;

    const int c0 = tid, c1 = tid + 256;
    const int ar0 = c0 >> 2, as0 = (c0 & 3) * 8;
    const int ar1 = c1 >> 2, as1 = (c1 & 3) * 8;

    const unsigned sBase = sptr(&sh.t[0][0][0][0]);
    const unsigned stgStride = 2 * 128 * 40 * 2;
    const unsigned bOff = 128 * 40 * 2;

    auto issue = [&](int kb, int st) {
        const __half* Ag = A + (size_t)bm * DD + kb * 32;
        const __half* Bg = W + (size_t)bn * DD + kb * 32;
        unsigned s = sBase + st * stgStride;
        cpa16(s + (unsigned)(ar0 * 40 + as0) * 2, Ag + (size_t)ar0 * DD + as0);
        cpa16(s + (unsigned)(ar1 * 40 + as1) * 2, Ag + (size_t)ar1 * DD + as1);
        cpa16(s + bOff + (unsigned)(ar0 * 40 + as0) * 2, Bg + (size_t)ar0 * DD + as0);
        cpa16(s + bOff + (unsigned)(ar1 * 40 + as1) * 2, Bg + (size_t)ar1 * DD + as1);
        cpa_commit();
    };

    float acc[4][4][4];
#pragma unroll
    for (int mt = 0; mt < 4; mt++)
#pragma unroll
        for (int nt = 0; nt < 4; nt++)
#pragma unroll
            for (int r = 0; r < 4; r++) acc[mt][nt][r] = 0.f;

    const int a_r = l & 15, a_c = (l >> 4) * 8;
    const int b_r = (l & 7) | ((l >> 1) & 8), b_c = l & 8;

    issue(0, 0);
    issue(1, 1);

    const int NKB = DD / 32;
    for (int kb = 0; kb < NKB; kb++) {
        const int st = kb % 3;
        if (kb == NKB - 1) cpa_wait<0>(); else cpa_wait<1>();
        __syncthreads();
        if (kb + 2 < NKB) issue(kb + 2, (kb + 2) % 3);

        const unsigned sA = sBase + st * stgStride;
        const unsigned sB = sA + bOff;
#pragma unroll
        for (int ks = 0; ks < 2; ks++) {
            unsigned a[4][4], bfr[2][4];
#pragma unroll
            for (int mt = 0; mt < 4; mt++) {
                int r = wm * 64 + mt * 16 + a_r;
                int c = ks * 16 + a_c;
                ldsm4(a[mt][0], a[mt][1], a[mt][2], a[mt][3],
                      sA + (unsigned)(r * 40 + c) * 2);
            }
#pragma unroll
            for (int np = 0; np < 2; np++) {
                int r = wn * 32 + np * 16 + b_r;
                int c = ks * 16 + b_c;
                ldsm4(bfr[np][0], bfr[np][1], bfr[np][2], bfr[np][3],
                      sB + (unsigned)(r * 40 + c) * 2);
            }
#pragma unroll
            for (int mt = 0; mt < 4; mt++)
#pragma unroll
                for (int nt = 0; nt < 4; nt++)
                    mma16816(acc[mt][nt], a[mt][0], a[mt][1], a[mt][2], a[mt][3],
                             bfr[nt >> 1][(nt & 1) * 2], bfr[nt >> 1][(nt & 1) * 2 + 1]);
        }
    }
    __syncthreads();

#pragma unroll
    for (int nt = 0; nt < 4; nt++) {
        int c0v = wn * 32 + nt * 8 + 2 * (l & 3);
        float bv0 = bias[bn + c0v], bv1 = bias[bn + c0v + 1];
#pragma unroll
        for (int mt = 0; mt < 4; mt++) {
            int r0 = wm * 64 + mt * 16 + (l >> 2);
            *(__half2*)&sh.C[r0][c0v]     = __floats2half2_rn(acc[mt][nt][0] + bv0, acc[mt][nt][1] + bv1);
            *(__half2*)&sh.C[r0 + 8][c0v] = __floats2half2_rn(acc[mt][nt][2] + bv0, acc[mt][nt][3] + bv1);
        }
    }
    __syncthreads();

    const int h = tid & 15, sg = tid >> 4;
#pragma unroll
    for (int sl = 0; sl < 8; sl++) {
        int s = sg * 8 + sl;
        int m = bm + s;
        int b_ = m >> 11, sloc = m & 2047;
        __half tmp[8];
#pragma unroll
        for (int dd = 0; dd < 8; dd++) tmp[dd] = sh.C[s][h + 16 * dd];
        *(uint4*)&out[(((size_t)(b_ * NHH + h)) * SS + sloc) * DHH + (bn >> 4)] = *(uint4*)tmp;
    }
}

// ---------------------------------------------------------------------------
// FULLY FUSED attention v6: ICH=32 (64 iters), single-buffered K & V, single
// S buffer, 3 phases/iter. Q in registers. Softmax: half2 over i-pairs, all
// 512 threads active, __expf (R12 numerics).
// smem (halves): K[16h][32i][72] 36864 | V same 36864 | S[16h][32k][40] 20480
// = 94208 halves = 188,416 B, 1 CTA/SM.
// Ledger: prologue Q(g),K0(g). top(c): wait<0> (K[c]); bar; issue V[c].
// A: score. bar. issue K[c+1]; softmax; wait<1> (V[c]); bar. B: AV[c].
// ---------------------------------------------------------------------------
#define ICH 32
#define NIT (SS / ICH)
__global__ void __launch_bounds__(512, 1) attn_fused() {
    extern __shared__ __half sm[];
    __half* Ss = sm + 2 * 36864;            // S: 16x32x40

    const int b = blockIdx.y;
    const int kbase = blockIdx.x * 32;
    const int tid = threadIdx.x;
    const int h = tid >> 5;                 // warp = head
    const int l = tid & 31;

    const unsigned sK = sptr(sm);
    const unsigned sV = sK + 36864u * 2;
    const unsigned sS = sV + 36864u * 2;

    const int a_r = l & 15, a_c = (l >> 4) * 8;
    const int b_r = (l & 7) | ((l >> 1) & 8), b_c = l & 8;
    const int bt_r = (l & 7) + ((l >> 3) & 1) * 8;
    const int bt_c = ((l >> 4) & 1) * 8;

    const __half* Kg = g_Kh + (size_t)(b * NHH) * SS * DHH;
    const __half* Qg = g_Qh + (size_t)(b * NHH) * SS * DHH;
    const __half* Vg = g_Vh + (size_t)(b * NHH) * SS * DHH;

    // chunk loader: 512 rows (h2*32 + i_local), 8 segs/row, 8 cpa/thread
    auto loadChunk = [&](const __half* src, unsigned dstbase, int ig0) {
#pragma unroll
        for (int t = 0; t < 8; t++) {
            int id = tid + t * 512;
            int row = id >> 3;
            int seg = (id & 7) * 8;
            int h2 = row >> 5, il = row & 31;
            cpa16(dstbase + (unsigned)(row * 72 + seg) * 2,
                  src + ((size_t)h2 * SS + ig0 + il) * DHH + seg);
        }
        cpa_commit();
    };

    // ---- prologue: Q staged into V region (group 1), K[0] (group 2) ----
#pragma unroll
    for (int t = 0; t < 8; t++) {
        int id = tid + t * 512;
        int row = id >> 3;                 // h*32 + k_local
        int seg = (id & 7) * 8;
        int h2 = row >> 5, kl = row & 31;
        cpa16(sV + (unsigned)(row * 72 + seg) * 2,
              Qg + ((size_t)h2 * SS + kbase + kl) * DHH + seg);
    }
    cpa_commit();
    loadChunk(Kg, sK, 0);
    cpa_wait<1>();                 // Q done (K0 may be in flight)
    __syncthreads();

    // ---- Q -> registers ----
    unsigned aq[2][4][4];
#pragma unroll
    for (int mt = 0; mt < 2; mt++)
#pragma unroll
        for (int ks = 0; ks < 4; ks++)
            ldsm4(aq[mt][ks][0], aq[mt][ks][1], aq[mt][ks][2], aq[mt][ks][3],
                  sV + (unsigned)((h * 32 + mt * 16 + a_r) * 72 + ks * 16 + a_c) * 2);
    __syncthreads();               // Q reads done -> V region free

    float oacc[2][8][4];
#pragma unroll
    for (int mt = 0; mt < 2; mt++)
#pragma unroll
        for (int nt = 0; nt < 8; nt++)
#pragma unroll
            for (int r = 0; r < 4; r++) oacc[mt][nt][r] = 0.f;

    for (int c = 0; c < NIT; c++) {
        // ---- top: K[c] complete; V[c-1]/S reads finished at prior barrier ----
        cpa_wait<0>();
        __syncthreads();
        loadChunk(Vg, sV, c * ICH);

        // ---- phase A: score[c] on K[c] -> S raw (stride 40) ----
        {
            float sacc[2][4][4];
#pragma unroll
            for (int mt = 0; mt < 2; mt++)
#pragma unroll
                for (int nt = 0; nt < 4; nt++)
#pragma unroll
                    for (int r = 0; r < 4; r++) sacc[mt][nt][r] = 0.f;

#pragma unroll
            for (int ks = 0; ks < 4; ks++) {
                unsigned bk4[2][4];
#pragma unroll
                for (int np = 0; np < 2; np++)
                    ldsm4(bk4[np][0], bk4[np][1], bk4[np][2], bk4[np][3],
                          sK + (unsigned)((h * 32 + np * 16 + b_r) * 72 + ks * 16 + b_c) * 2);
#pragma unroll
                for (int mt = 0; mt < 2; mt++)
#pragma unroll
                    for (int nt = 0; nt < 4; nt++)
                        mma16816(sacc[mt][nt],
                                 aq[mt][ks][0], aq[mt][ks][1], aq[mt][ks][2], aq[mt][ks][3],
                                 bk4[nt >> 1][(nt & 1) * 2], bk4[nt >> 1][(nt & 1) * 2 + 1]);
            }
#pragma unroll
            for (int mt = 0; mt < 2; mt++)
#pragma unroll
                for (int nt = 0; nt < 4; nt++) {
                    int r = mt * 16 + (l >> 2);
                    int cc = nt * 8 + 2 * (l & 3);
                    *(__half2*)&Ss[(h * 32 + r) * 40 + cc] =
                        __floats2half2_rn(sacc[mt][nt][0] * 0.125f, sacc[mt][nt][1] * 0.125f);
                    *(__half2*)&Ss[(h * 32 + r + 8) * 40 + cc] =
                        __floats2half2_rn(sacc[mt][nt][2] * 0.125f, sacc[mt][nt][3] * 0.125f);
                }
        }
        __syncthreads();   // S raw visible; K reads done -> K reusable

        // ---- phase S: issue K[c+1]; softmax (half2, all threads); wait V ----
        if (c + 1 < NIT) loadChunk(Kg, sK, (c + 1) * ICH);
        {
            int kq = tid >> 4;            // 0..31
            int ix = (tid & 15) * 2;      // i-pair 0..30
            float2 v[NHH];
            float mx = -1e30f;
#pragma unroll
            for (int h2 = 0; h2 < NHH; h2++) {
                v[h2] = __half22float2(*(__half2*)&Ss[(h2 * 32 + kq) * 40 + ix]);
                mx = fmaxf(mx, fmaxf(v[h2].x, v[h2].y));
            }
            float sx = 0.f, sy = 0.f;
#pragma unroll
            for (int h2 = 0; h2 < NHH; h2++) {
                v[h2].x = __expf(v[h2].x - mx);
                v[h2].y = __expf(v[h2].y - mx);
                sx += v[h2].x;
                sy += v[h2].y;
            }
            float ivx = 1.f / sx, ivy = 1.f / sy;
#pragma unroll
            for (int h2 = 0; h2 < NHH; h2++)
                *(__half2*)&Ss[(h2 * 32 + kq) * 40 + ix] =
                    __floats2half2_rn(v[h2].x * ivx, v[h2].y * ivy);
        }
        if (c + 1 < NIT) cpa_wait<1>(); else cpa_wait<0>();   // V[c] done
        __syncthreads();   // S normalized + V ready

        // ---- phase B: AV[c] ----
#pragma unroll
        for (int ks = 0; ks < 2; ks++) {
            unsigned as4[2][4], bv[4][4];
#pragma unroll
            for (int mt = 0; mt < 2; mt++)
                ldsm4(as4[mt][0], as4[mt][1], as4[mt][2], as4[mt][3],
                      sS + (unsigned)((h * 32 + mt * 16 + a_r) * 40 + ks * 16 + a_c) * 2);
#pragma unroll
            for (int np = 0; np < 4; np++)
                ldsm4t(bv[np][0], bv[np][1], bv[np][2], bv[np][3],
                       sV + (unsigned)((h * 32 + ks * 16 + bt_r) * 72 + np * 16 + bt_c) * 2);
#pragma unroll
            for (int mt = 0; mt < 2; mt++)
#pragma unroll
                for (int nt = 0; nt < 8; nt++)
                    mma16816(oacc[mt][nt], as4[mt][0], as4[mt][1], as4[mt][2], as4[mt][3],
                             bv[nt >> 1][(nt & 1) * 2], bv[nt >> 1][(nt & 1) * 2 + 1]);
        }
        // next iteration's top barrier separates V/S overwrites from these reads
    }
    __syncthreads();

    // ---- epilogue: stage O to smem [ch=16j+h][k stride 40], uint4 writeout --
    __half* Osm = sm;
#pragma unroll
    for (int mt = 0; mt < 2; mt++) {
        int k0 = mt * 16 + (l >> 2);
#pragma unroll
        for (int nt = 0; nt < 8; nt++) {
            int j0 = nt * 8 + 2 * (l & 3);
            Osm[(16 * j0 + h) * 40 + k0]           = __float2half_rn(oacc[mt][nt][0]);
            Osm[(16 * (j0 + 1) + h) * 40 + k0]     = __float2half_rn(oacc[mt][nt][1]);
            Osm[(16 * j0 + h) * 40 + k0 + 8]       = __float2half_rn(oacc[mt][nt][2]);
            Osm[(16 * (j0 + 1) + h) * 40 + k0 + 8] = __float2half_rn(oacc[mt][nt][3]);
        }
    }
    __syncthreads();

    __half* Xb = g_Xt + (size_t)b * HH * SS;
#pragma unroll
    for (int e = 0; e < 8; e++) {
        int id = e * 512 + tid;
        int kseg = (id & 3) * 8;
        int cc = id >> 2;
        uint4 val = *(const uint4*)&Osm[cc * 40 + kseg];
        *(uint4*)&Xb[(size_t)cc * SS + kbase + kseg] = val;
    }
}

// ---------------------------------------------------------------------------
// Output projection: out = X @ Wo^T + bias, 3-stage cp.async.
// ---------------------------------------------------------------------------
__global__ void __launch_bounds__(256) outproj_gemm(const float* __restrict__ bias,
                                                    float* __restrict__ out) {
    const __half* Wo = g_W16[3];

    __shared__ __half At[3][32][72];
    __shared__ __half Bt[3][128][40];

    const int tid = threadIdx.x;
    const int bm = blockIdx.y * 64, bn = blockIdx.x * 128;
    const int b_ = bm >> 11, sbase = bm & 2047;
    const int w = tid >> 5, l = tid & 31;
    const int wm = w >> 2, wn = w & 3;

    const int arow = tid >> 3, aseg = (tid & 7) * 8;
    const int bc0 = tid, bc1 = tid + 256;
    const int br0 = bc0 >> 2, bs0 = (bc0 & 3) * 8;
    const int br1 = bc1 >> 2, bs1 = (bc1 & 3) * 8;

    const int at_r = (l & 7) + ((l >> 4) & 1) * 8;
    const int at_c = ((l >> 3) & 1) * 8;
    const int b_r = (l & 7) | ((l >> 1) & 8), b_c = l & 8;

    const unsigned sAt = sptr(&At[0][0][0]);
    const unsigned sBt = sptr(&Bt[0][0][0]);
    const unsigned Abs = 32 * 72 * 2, Bbs = 128 * 40 * 2;

    const __half* Abase = g_Xt + (size_t)b_ * HH * SS + sbase;

    auto issue = [&](int kb, int st) {
        cpa16(sAt + st * Abs + (unsigned)(arow * 72 + aseg) * 2,
              Abase + (size_t)(kb * 32 + arow) * SS + aseg);
        cpa16(sBt + st * Bbs + (unsigned)(br0 * 40 + bs0) * 2,
              Wo + (size_t)(bn + br0) * HH + kb * 32 + bs0);
        cpa16(sBt + st * Bbs + (unsigned)(br1 * 40 + bs1) * 2,
              Wo + (size_t)(bn + br1) * HH + kb * 32 + bs1);
        cpa_commit();
    };

    float acc[2][4][4];
#pragma unroll
    for (int mt = 0; mt < 2; mt++)
#pragma unroll
        for (int nt = 0; nt < 4; nt++)
#pragma unroll
            for (int r = 0; r < 4; r++) acc[mt][nt][r] = 0.f;

    issue(0, 0);
    issue(1, 1);

    const int NKB = HH / 32;
    for (int kb = 0; kb < NKB; kb++) {
        const int st = kb % 3;
        if (kb == NKB - 1) cpa_wait<0>(); else cpa_wait<1>();
        __syncthreads();
        if (kb + 2 < NKB) issue(kb + 2, (kb + 2) % 3);

#pragma unroll
        for (int ks = 0; ks < 2; ks++) {
            unsigned a[2][4], bfr[2][4];
#pragma unroll
            for (int mt = 0; mt < 2; mt++) {
                int r = ks * 16 + at_r;
                int c = wm * 32 + mt * 16 + at_c;
                ldsm4t(a[mt][0], a[mt][1], a[mt][2], a[mt][3],
                       sAt + st * Abs + (unsigned)(r * 72 + c) * 2);
            }
#pragma unroll
            for (int np = 0; np < 2; np++) {
                int r = wn * 32 + np * 16 + b_r;
                int c = ks * 16 + b_c;
                ldsm4(bfr[np][0], bfr[np][1], bfr[np][2], bfr[np][3],
                      sBt + st * Bbs + (unsigned)(r * 40 + c) * 2);
            }
#pragma unroll
            for (int mt = 0; mt < 2; mt++)
#pragma unroll
                for (int nt = 0; nt < 4; nt++)
                    mma16816(acc[mt][nt], a[mt][0], a[mt][1], a[mt][2], a[mt][3],
                             bfr[nt >> 1][(nt & 1) * 2], bfr[nt >> 1][(nt & 1) * 2 + 1]);
        }
        __syncthreads();
    }

#pragma unroll
    for (int nt = 0; nt < 4; nt++) {
        int c0 = bn + wn * 32 + nt * 8 + 2 * (l & 3);
        float bv0 = bias[c0], bv1 = bias[c0 + 1];
#pragma unroll
        for (int mt = 0; mt < 2; mt++) {
            int r0 = bm + wm * 32 + mt * 16 + (l >> 2);
            float2 v0 = make_float2(acc[mt][nt][0] + bv0, acc[mt][nt][1] + bv1);
            float2 v1 = make_float2(acc[mt][nt][2] + bv0, acc[mt][nt][3] + bv1);
            *(float2*)&out[(size_t)r0 * HH + c0] = v0;
            *(float2*)&out[(size_t)(r0 + 8) * HH + c0] = v1;
        }
    }
}

// ---------------------------------------------------------------------------
// Launch
// ---------------------------------------------------------------------------
extern "C" void kernel_launch(void* const* d_in, const int* in_sizes, int n_in,
                              void* d_out, int out_size)
{
    const float* KEY   = (const float*)d_in[0];
    const float* VALUE = (const float*)d_in[1];
    const float* QUERY = (const float*)d_in[2];
    const float* Wk_w  = (const float*)d_in[3];
    const float* Wk_b  = (const float*)d_in[4];
    const float* Wq_w  = (const float*)d_in[5];
    const float* Wq_b  = (const float*)d_in[6];
    const float* Wv_w  = (const float*)d_in[7];
    const float* Wv_b  = (const float*)d_in[8];
    const float* Wo_w  = (const float*)d_in[9];
    const float* Wo_b  = (const float*)d_in[10];
    float* out = (float*)d_out;

    const int fsm = (36864 + 36864 + 20480) * 2;   // 188,416 B
    static bool attr_done = false;
    if (!attr_done) {
        cudaFuncSetAttribute(attn_fused, cudaFuncAttributeMaxDynamicSharedMemorySize, fsm);
        attr_done = true;
    }

    cvt_all<<<TOT4 / 512, 256>>>((const float4*)KEY, (const float4*)QUERY,
                                 (const float4*)VALUE, (const float4*)Wk_w,
                                 (const float4*)Wq_w, (const float4*)Wv_w,
                                 (const float4*)Wo_w);

    dim3 pg(HH / 128, (BB * SS) / 128, 3);         // 768 CTAs
    proj_fused<<<pg, 256>>>(Wk_b, Wq_b, Wv_b);

    dim3 fg(SS / 32, BB);                          // (64, 2) = 128 CTAs
    attn_fused<<<fg, 512, fsm>>>();

    dim3 og(HH / 128, (BB * SS) / 64);             // (8, 64)
    outproj_gemm<<<og, 256>>>(Wo_b, out);
}

// round 16
// speedup vs baseline: 1.1237x; 1.0357x over previous
#include <cuda_runtime.h>
#include <cuda_fp16.h>

#define BB  2
#define SS  2048
#define DD  1024
#define HH  1024
#define NHH 16
#define DHH 64

// 1/8 (dh scale) folded with log2(e) so softmax can use bare exp2f
#define SC_PRE 0.1803368801111204f

// ---------------------------------------------------------------------------
// Static scratch
// ---------------------------------------------------------------------------
__device__ __half g_A16[3][BB * SS * DD];          // fp16 KEY, QUERY, VALUE
__device__ __half g_W16[4][HH * DD];               // fp16 Wk, Wq, Wv, Wo
__device__ __half g_Kh[BB * NHH * SS * DHH];       // head-split projections
__device__ __half g_Qh[BB * NHH * SS * DHH];
__device__ __half g_Vh[BB * NHH * SS * DHH];
__device__ __half g_Xt[BB * HH * SS];              // X transposed [b][c][s]

// ---------------------------------------------------------------------------
// PTX helpers
// ---------------------------------------------------------------------------
__device__ __forceinline__ unsigned sptr(const void* p) {
    unsigned a;
    asm("{.reg .u64 t; cvta.to.shared.u64 t, %1; cvt.u32.u64 %0, t;}" : "=r"(a) : "l"(p));
    return a;
}
__device__ __forceinline__ void ldsm4(unsigned& r0, unsigned& r1, unsigned& r2, unsigned& r3, unsigned a) {
    asm volatile("ldmatrix.sync.aligned.m8n8.x4.shared.b16 {%0,%1,%2,%3},[%4];\n"
                 : "=r"(r0), "=r"(r1), "=r"(r2), "=r"(r3) : "r"(a));
}
__device__ __forceinline__ void ldsm4t(unsigned& r0, unsigned& r1, unsigned& r2, unsigned& r3, unsigned a) {
    asm volatile("ldmatrix.sync.aligned.m8n8.x4.trans.shared.b16 {%0,%1,%2,%3},[%4];\n"
                 : "=r"(r0), "=r"(r1), "=r"(r2), "=r"(r3) : "r"(a));
}
__device__ __forceinline__ void mma16816(float* c, unsigned a0, unsigned a1, unsigned a2, unsigned a3,
                                         unsigned b0, unsigned b1) {
    asm volatile("mma.sync.aligned.m16n8k16.row.col.f32.f16.f16.f32 "
                 "{%0,%1,%2,%3},{%4,%5,%6,%7},{%8,%9},{%0,%1,%2,%3};\n"
                 : "+f"(c[0]), "+f"(c[1]), "+f"(c[2]), "+f"(c[3])
                 : "r"(a0), "r"(a1), "r"(a2), "r"(a3), "r"(b0), "r"(b1));
}
__device__ __forceinline__ void cpa16(unsigned d, const void* s) {
    asm volatile("cp.async.cg.shared.global [%0],[%1],16;\n" :: "r"(d), "l"(s));
}
__device__ __forceinline__ void cpa_commit() { asm volatile("cp.async.commit_group;\n"); }
template <int N> __device__ __forceinline__ void cpa_wait() {
    asm volatile("cp.async.wait_group %0;\n" :: "n"(N));
}

// ---------------------------------------------------------------------------
// Fused fp32->fp16 conversion, 4 float4 per thread (MLP 4).
// ---------------------------------------------------------------------------
#define IN4 (BB * SS * DD / 4)
#define W4  (HH * DD / 4)
#define TOT4 (3 * IN4 + 4 * W4)
__global__ void __launch_bounds__(256) cvt_all(const float4* __restrict__ k,
                                               const float4* __restrict__ q,
                                               const float4* __restrict__ v,
                                               const float4* __restrict__ wk,
                                               const float4* __restrict__ wq,
                                               const float4* __restrict__ wv,
                                               const float4* __restrict__ wo)
{
    float4 val[4];
    __half2* dsts[4];
    int lis[4];
#pragma unroll
    for (int e = 0; e < 4; e++) {
        int idx = (blockIdx.x * 4 + e) * 256 + threadIdx.x;
        const float4* src;
        int li;
        if (idx < 3 * IN4) {
            int which = idx / IN4;
            li = idx - which * IN4;
            src = (which == 0) ? k : (which == 1) ? q : v;
            dsts[e] = (__half2*)g_A16[which];
        } else {
            int r = idx - 3 * IN4;
            int which = r / W4;
            li = r - which * W4;
            src = (which == 0) ? wk : (which == 1) ? wq : (which == 2) ? wv : wo;
            dsts[e] = (__half2*)g_W16[which];
        }
        lis[e] = li;
        val[e] = src[li];
    }
#pragma unroll
    for (int e = 0; e < 4; e++) {
        dsts[e][lis[e] * 2]     = __floats2half2_rn(val[e].x, val[e].y);
        dsts[e][lis[e] * 2 + 1] = __floats2half2_rn(val[e].z, val[e].w);
    }
}

// ---------------------------------------------------------------------------
// Fused projection GEMM (K, Q, V; which = blockIdx.z). BM=128 BN=128 BK=32.
// ---------------------------------------------------------------------------
__global__ void __launch_bounds__(256) proj_fused(const float* __restrict__ bk,
                                                  const float* __restrict__ bq,
                                                  const float* __restrict__ bv) {
    const int which = blockIdx.z;
    const __half* A = g_A16[which];
    const __half* W = g_W16[which];
    __half* out = (which == 0) ? g_Kh : (which == 1) ? g_Qh : g_Vh;
    const float* bias = (which == 0) ? bk : (which == 1) ? bq : bv;

    __shared__ union {
        __half t[3][2][128][40];
        __half C[128][136];
    } sh;

    const int tid = threadIdx.x;
    const int bm = blockIdx.y * 128, bn = blockIdx.x * 128;
    const int w = tid >> 5, l = tid & 31;
    const int wm = w >> 2, wn = w & 3;

    const int c0 = tid, c1 = tid + 256;
    const int ar0 = c0 >> 2, as0 = (c0 & 3) * 8;
    const int ar1 = c1 >> 2, as1 = (c1 & 3) * 8;

    const unsigned sBase = sptr(&sh.t[0][0][0][0]);
    const unsigned stgStride = 2 * 128 * 40 * 2;
    const unsigned bOff = 128 * 40 * 2;

    auto issue = [&](int kb, int st) {
        const __half* Ag = A + (size_t)bm * DD + kb * 32;
        const __half* Bg = W + (size_t)bn * DD + kb * 32;
        unsigned s = sBase + st * stgStride;
        cpa16(s + (unsigned)(ar0 * 40 + as0) * 2, Ag + (size_t)ar0 * DD + as0);
        cpa16(s + (unsigned)(ar1 * 40 + as1) * 2, Ag + (size_t)ar1 * DD + as1);
        cpa16(s + bOff + (unsigned)(ar0 * 40 + as0) * 2, Bg + (size_t)ar0 * DD + as0);
        cpa16(s + bOff + (unsigned)(ar1 * 40 + as1) * 2, Bg + (size_t)ar1 * DD + as1);
        cpa_commit();
    };

    float acc[4][4][4];
#pragma unroll
    for (int mt = 0; mt < 4; mt++)
#pragma unroll
        for (int nt = 0; nt < 4; nt++)
#pragma unroll
            for (int r = 0; r < 4; r++) acc[mt][nt][r] = 0.f;

    const int a_r = l & 15, a_c = (l >> 4) * 8;
    const int b_r = (l & 7) | ((l >> 1) & 8), b_c = l & 8;

    issue(0, 0);
    issue(1, 1);

    const int NKB = DD / 32;
    for (int kb = 0; kb < NKB; kb++) {
        const int st = kb % 3;
        if (kb == NKB - 1) cpa_wait<0>(); else cpa_wait<1>();
        __syncthreads();
        if (kb + 2 < NKB) issue(kb + 2, (kb + 2) % 3);

        const unsigned sA = sBase + st * stgStride;
        const unsigned sB = sA + bOff;
#pragma unroll
        for (int ks = 0; ks < 2; ks++) {
            unsigned a[4][4], bfr[2][4];
#pragma unroll
            for (int mt = 0; mt < 4; mt++) {
                int r = wm * 64 + mt * 16 + a_r;
                int c = ks * 16 + a_c;
                ldsm4(a[mt][0], a[mt][1], a[mt][2], a[mt][3],
                      sA + (unsigned)(r * 40 + c) * 2);
            }
#pragma unroll
            for (int np = 0; np < 2; np++) {
                int r = wn * 32 + np * 16 + b_r;
                int c = ks * 16 + b_c;
                ldsm4(bfr[np][0], bfr[np][1], bfr[np][2], bfr[np][3],
                      sB + (unsigned)(r * 40 + c) * 2);
            }
#pragma unroll
            for (int mt = 0; mt < 4; mt++)
#pragma unroll
                for (int nt = 0; nt < 4; nt++)
                    mma16816(acc[mt][nt], a[mt][0], a[mt][1], a[mt][2], a[mt][3],
                             bfr[nt >> 1][(nt & 1) * 2], bfr[nt >> 1][(nt & 1) * 2 + 1]);
        }
    }
    __syncthreads();

#pragma unroll
    for (int nt = 0; nt < 4; nt++) {
        int c0v = wn * 32 + nt * 8 + 2 * (l & 3);
        float bv0 = bias[bn + c0v], bv1 = bias[bn + c0v + 1];
#pragma unroll
        for (int mt = 0; mt < 4; mt++) {
            int r0 = wm * 64 + mt * 16 + (l >> 2);
            *(__half2*)&sh.C[r0][c0v]     = __floats2half2_rn(acc[mt][nt][0] + bv0, acc[mt][nt][1] + bv1);
            *(__half2*)&sh.C[r0 + 8][c0v] = __floats2half2_rn(acc[mt][nt][2] + bv0, acc[mt][nt][3] + bv1);
        }
    }
    __syncthreads();

    const int h = tid & 15, sg = tid >> 4;
#pragma unroll
    for (int sl = 0; sl < 8; sl++) {
        int s = sg * 8 + sl;
        int m = bm + s;
        int b_ = m >> 11, sloc = m & 2047;
        __half tmp[8];
#pragma unroll
        for (int dd = 0; dd < 8; dd++) tmp[dd] = sh.C[s][h + 16 * dd];
        *(uint4*)&out[(((size_t)(b_ * NHH + h)) * SS + sloc) * DHH + (bn >> 4)] = *(uint4*)tmp;
    }
}

// ---------------------------------------------------------------------------
// FULLY FUSED attention v7 (= v6 + exp2-fold + no-max softmax).
// ICH=32 (64 iters), single-buffered K & V, single S buffer, 3 phases/iter.
// Q in registers. Softmax: half2 over i-pairs, 512 threads, bare exp2f, no
// max subtraction (|score*0.125| << fp32 exp range).
// smem (halves): K 36864 | V 36864 | S[16h][32k][40] 20480 = 188,416 B.
// ---------------------------------------------------------------------------
#define ICH 32
#define NIT (SS / ICH)
__global__ void __launch_bounds__(512, 1) attn_fused() {
    extern __shared__ __half sm[];
    __half* Ss = sm + 2 * 36864;            // S: 16x32x40

    const int b = blockIdx.y;
    const int kbase = blockIdx.x * 32;
    const int tid = threadIdx.x;
    const int h = tid >> 5;                 // warp = head
    const int l = tid & 31;

    const unsigned sK = sptr(sm);
    const unsigned sV = sK + 36864u * 2;
    const unsigned sS = sV + 36864u * 2;

    const int a_r = l & 15, a_c = (l >> 4) * 8;
    const int b_r = (l & 7) | ((l >> 1) & 8), b_c = l & 8;
    const int bt_r = (l & 7) + ((l >> 3) & 1) * 8;
    const int bt_c = ((l >> 4) & 1) * 8;

    const __half* Kg = g_Kh + (size_t)(b * NHH) * SS * DHH;
    const __half* Qg = g_Qh + (size_t)(b * NHH) * SS * DHH;
    const __half* Vg = g_Vh + (size_t)(b * NHH) * SS * DHH;

    auto loadChunk = [&](const __half* src, unsigned dstbase, int ig0) {
#pragma unroll
        for (int t = 0; t < 8; t++) {
            int id = tid + t * 512;
            int row = id >> 3;
            int seg = (id & 7) * 8;
            int h2 = row >> 5, il = row & 31;
            cpa16(dstbase + (unsigned)(row * 72 + seg) * 2,
                  src + ((size_t)h2 * SS + ig0 + il) * DHH + seg);
        }
        cpa_commit();
    };

    // ---- prologue: Q staged into V region (group 1), K[0] (group 2) ----
#pragma unroll
    for (int t = 0; t < 8; t++) {
        int id = tid + t * 512;
        int row = id >> 3;
        int seg = (id & 7) * 8;
        int h2 = row >> 5, kl = row & 31;
        cpa16(sV + (unsigned)(row * 72 + seg) * 2,
              Qg + ((size_t)h2 * SS + kbase + kl) * DHH + seg);
    }
    cpa_commit();
    loadChunk(Kg, sK, 0);
    cpa_wait<1>();
    __syncthreads();

    // ---- Q -> registers ----
    unsigned aq[2][4][4];
#pragma unroll
    for (int mt = 0; mt < 2; mt++)
#pragma unroll
        for (int ks = 0; ks < 4; ks++)
            ldsm4(aq[mt][ks][0], aq[mt][ks][1], aq[mt][ks][2], aq[mt][ks][3],
                  sV + (unsigned)((h * 32 + mt * 16 + a_r) * 72 + ks * 16 + a_c) * 2);
    __syncthreads();

    float oacc[2][8][4];
#pragma unroll
    for (int mt = 0; mt < 2; mt++)
#pragma unroll
        for (int nt = 0; nt < 8; nt++)
#pragma unroll
            for (int r = 0; r < 4; r++) oacc[mt][nt][r] = 0.f;

    for (int c = 0; c < NIT; c++) {
        cpa_wait<0>();
        __syncthreads();
        loadChunk(Vg, sV, c * ICH);

        // ---- phase A: score[c] on K[c] -> S raw, pre-scaled to exp2 domain --
        {
            float sacc[2][4][4];
#pragma unroll
            for (int mt = 0; mt < 2; mt++)
#pragma unroll
                for (int nt = 0; nt < 4; nt++)
#pragma unroll
                    for (int r = 0; r < 4; r++) sacc[mt][nt][r] = 0.f;

#pragma unroll
            for (int ks = 0; ks < 4; ks++) {
                unsigned bk4[2][4];
#pragma unroll
                for (int np = 0; np < 2; np++)
                    ldsm4(bk4[np][0], bk4[np][1], bk4[np][2], bk4[np][3],
                          sK + (unsigned)((h * 32 + np * 16 + b_r) * 72 + ks * 16 + b_c) * 2);
#pragma unroll
                for (int mt = 0; mt < 2; mt++)
#pragma unroll
                    for (int nt = 0; nt < 4; nt++)
                        mma16816(sacc[mt][nt],
                                 aq[mt][ks][0], aq[mt][ks][1], aq[mt][ks][2], aq[mt][ks][3],
                                 bk4[nt >> 1][(nt & 1) * 2], bk4[nt >> 1][(nt & 1) * 2 + 1]);
            }
#pragma unroll
            for (int mt = 0; mt < 2; mt++)
#pragma unroll
                for (int nt = 0; nt < 4; nt++) {
                    int r = mt * 16 + (l >> 2);
                    int cc = nt * 8 + 2 * (l & 3);
                    *(__half2*)&Ss[(h * 32 + r) * 40 + cc] =
                        __floats2half2_rn(sacc[mt][nt][0] * SC_PRE, sacc[mt][nt][1] * SC_PRE);
                    *(__half2*)&Ss[(h * 32 + r + 8) * 40 + cc] =
                        __floats2half2_rn(sacc[mt][nt][2] * SC_PRE, sacc[mt][nt][3] * SC_PRE);
                }
        }
        __syncthreads();   // S raw visible; K reads done -> K reusable

        // ---- phase S: issue K[c+1]; softmax (exp2, no max); wait V ----
        if (c + 1 < NIT) loadChunk(Kg, sK, (c + 1) * ICH);
        {
            int kq = tid >> 4;            // 0..31
            int ix = (tid & 15) * 2;      // i-pair
            float2 e[NHH];
            float sx = 0.f, sy = 0.f;
#pragma unroll
            for (int h2 = 0; h2 < NHH; h2++) {
                float2 v = __half22float2(*(__half2*)&Ss[(h2 * 32 + kq) * 40 + ix]);
                e[h2].x = exp2f(v.x);
                e[h2].y = exp2f(v.y);
                sx += e[h2].x;
                sy += e[h2].y;
            }
            float ivx = 1.f / sx, ivy = 1.f / sy;
#pragma unroll
            for (int h2 = 0; h2 < NHH; h2++)
                *(__half2*)&Ss[(h2 * 32 + kq) * 40 + ix] =
                    __floats2half2_rn(e[h2].x * ivx, e[h2].y * ivy);
        }
        if (c + 1 < NIT) cpa_wait<1>(); else cpa_wait<0>();
        __syncthreads();   // S normalized + V ready

        // ---- phase B: AV[c] ----
#pragma unroll
        for (int ks = 0; ks < 2; ks++) {
            unsigned as4[2][4], bv[4][4];
#pragma unroll
            for (int mt = 0; mt < 2; mt++)
                ldsm4(as4[mt][0], as4[mt][1], as4[mt][2], as4[mt][3],
                      sS + (unsigned)((h * 32 + mt * 16 + a_r) * 40 + ks * 16 + a_c) * 2);
#pragma unroll
            for (int np = 0; np < 4; np++)
                ldsm4t(bv[np][0], bv[np][1], bv[np][2], bv[np][3],
                       sV + (unsigned)((h * 32 + ks * 16 + bt_r) * 72 + np * 16 + bt_c) * 2);
#pragma unroll
            for (int mt = 0; mt < 2; mt++)
#pragma unroll
                for (int nt = 0; nt < 8; nt++)
                    mma16816(oacc[mt][nt], as4[mt][0], as4[mt][1], as4[mt][2], as4[mt][3],
                             bv[nt >> 1][(nt & 1) * 2], bv[nt >> 1][(nt & 1) * 2 + 1]);
        }
    }
    __syncthreads();

    // ---- epilogue: stage O to smem, uint4 writeout ----
    __half* Osm = sm;
#pragma unroll
    for (int mt = 0; mt < 2; mt++) {
        int k0 = mt * 16 + (l >> 2);
#pragma unroll
        for (int nt = 0; nt < 8; nt++) {
            int j0 = nt * 8 + 2 * (l & 3);
            Osm[(16 * j0 + h) * 40 + k0]           = __float2half_rn(oacc[mt][nt][0]);
            Osm[(16 * (j0 + 1) + h) * 40 + k0]     = __float2half_rn(oacc[mt][nt][1]);
            Osm[(16 * j0 + h) * 40 + k0 + 8]       = __float2half_rn(oacc[mt][nt][2]);
            Osm[(16 * (j0 + 1) + h) * 40 + k0 + 8] = __float2half_rn(oacc[mt][nt][3]);
        }
    }
    __syncthreads();

    __half* Xb = g_Xt + (size_t)b * HH * SS;
#pragma unroll
    for (int e = 0; e < 8; e++) {
        int id = e * 512 + tid;
        int kseg = (id & 3) * 8;
        int cc = id >> 2;
        uint4 val = *(const uint4*)&Osm[cc * 40 + kseg];
        *(uint4*)&Xb[(size_t)cc * SS + kbase + kseg] = val;
    }
}

// ---------------------------------------------------------------------------
// Output projection: out = X @ Wo^T + bias, 3-stage cp.async.
// ---------------------------------------------------------------------------
__global__ void __launch_bounds__(256) outproj_gemm(const float* __restrict__ bias,
                                                    float* __restrict__ out) {
    const __half* Wo = g_W16[3];

    __shared__ __half At[3][32][72];
    __shared__ __half Bt[3][128][40];

    const int tid = threadIdx.x;
    const int bm = blockIdx.y * 64, bn = blockIdx.x * 128;
    const int b_ = bm >> 11, sbase = bm & 2047;
    const int w = tid >> 5, l = tid & 31;
    const int wm = w >> 2, wn = w & 3;

    const int arow = tid >> 3, aseg = (tid & 7) * 8;
    const int bc0 = tid, bc1 = tid + 256;
    const int br0 = bc0 >> 2, bs0 = (bc0 & 3) * 8;
    const int br1 = bc1 >> 2, bs1 = (bc1 & 3) * 8;

    const int at_r = (l & 7) + ((l >> 4) & 1) * 8;
    const int at_c = ((l >> 3) & 1) * 8;
    const int b_r = (l & 7) | ((l >> 1) & 8), b_c = l & 8;

    const unsigned sAt = sptr(&At[0][0][0]);
    const unsigned sBt = sptr(&Bt[0][0][0]);
    const unsigned Abs = 32 * 72 * 2, Bbs = 128 * 40 * 2;

    const __half* Abase = g_Xt + (size_t)b_ * HH * SS + sbase;

    auto issue = [&](int kb, int st) {
        cpa16(sAt + st * Abs + (unsigned)(arow * 72 + aseg) * 2,
              Abase + (size_t)(kb * 32 + arow) * SS + aseg);
        cpa16(sBt + st * Bbs + (unsigned)(br0 * 40 + bs0) * 2,
              Wo + (size_t)(bn + br0) * HH + kb * 32 + bs0);
        cpa16(sBt + st * Bbs + (unsigned)(br1 * 40 + bs1) * 2,
              Wo + (size_t)(bn + br1) * HH + kb * 32 + bs1);
        cpa_commit();
    };

    float acc[2][4][4];
#pragma unroll
    for (int mt = 0; mt < 2; mt++)
#pragma unroll
        for (int nt = 0; nt < 4; nt++)
#pragma unroll
            for (int r = 0; r < 4; r++) acc[mt][nt][r] = 0.f;

    issue(0, 0);
    issue(1, 1);

    const int NKB = HH / 32;
    for (int kb = 0; kb < NKB; kb++) {
        const int st = kb % 3;
        if (kb == NKB - 1) cpa_wait<0>(); else cpa_wait<1>();
        __syncthreads();
        if (kb + 2 < NKB) issue(kb + 2, (kb + 2) % 3);

#pragma unroll
        for (int ks = 0; ks < 2; ks++) {
            unsigned a[2][4], bfr[2][4];
#pragma unroll
            for (int mt = 0; mt < 2; mt++) {
                int r = ks * 16 + at_r;
                int c = wm * 32 + mt * 16 + at_c;
                ldsm4t(a[mt][0], a[mt][1], a[mt][2], a[mt][3],
                       sAt + st * Abs + (unsigned)(r * 72 + c) * 2);
            }
#pragma unroll
            for (int np = 0; np < 2; np++) {
                int r = wn * 32 + np * 16 + b_r;
                int c = ks * 16 + b_c;
                ldsm4(bfr[np][0], bfr[np][1], bfr[np][2], bfr[np][3],
                      sBt + st * Bbs + (unsigned)(r * 40 + c) * 2);
            }
#pragma unroll
            for (int mt = 0; mt < 2; mt++)
#pragma unroll
                for (int nt = 0; nt < 4; nt++)
                    mma16816(acc[mt][nt], a[mt][0], a[mt][1], a[mt][2], a[mt][3],
                             bfr[nt >> 1][(nt & 1) * 2], bfr[nt >> 1][(nt & 1) * 2 + 1]);
        }
        __syncthreads();
    }

#pragma unroll
    for (int nt = 0; nt < 4; nt++) {
        int c0 = bn + wn * 32 + nt * 8 + 2 * (l & 3);
        float bv0 = bias[c0], bv1 = bias[c0 + 1];
#pragma unroll
        for (int mt = 0; mt < 2; mt++) {
            int r0 = bm + wm * 32 + mt * 16 + (l >> 2);
            float2 v0 = make_float2(acc[mt][nt][0] + bv0, acc[mt][nt][1] + bv1);
            float2 v1 = make_float2(acc[mt][nt][2] + bv0, acc[mt][nt][3] + bv1);
            *(float2*)&out[(size_t)r0 * HH + c0] = v0;
            *(float2*)&out[(size_t)(r0 + 8) * HH + c0] = v1;
        }
    }
}

// ---------------------------------------------------------------------------
// Launch
// ---------------------------------------------------------------------------
extern "C" void kernel_launch(void* const* d_in, const int* in_sizes, int n_in,
                              void* d_out, int out_size)
{
    const float* KEY   = (const float*)d_in[0];
    const float* VALUE = (const float*)d_in[1];
    const float* QUERY = (const float*)d_in[2];
    const float* Wk_w  = (const float*)d_in[3];
    const float* Wk_b  = (const float*)d_in[4];
    const float* Wq_w  = (const float*)d_in[5];
    const float* Wq_b  = (const float*)d_in[6];
    const float* Wv_w  = (const float*)d_in[7];
    const float* Wv_b  = (const float*)d_in[8];
    const float* Wo_w  = (const float*)d_in[9];
    const float* Wo_b  = (const float*)d_in[10];
    float* out = (float*)d_out;

    const int fsm = (36864 + 36864 + 20480) * 2;   // 188,416 B
    static bool attr_done = false;
    if (!attr_done) {
        cudaFuncSetAttribute(attn_fused, cudaFuncAttributeMaxDynamicSharedMemorySize, fsm);
        attr_done = true;
    }

    cvt_all<<<TOT4 / 1024, 256>>>((const float4*)KEY, (const float4*)QUERY,
                                  (const float4*)VALUE, (const float4*)Wk_w,
                                  (const float4*)Wq_w, (const float4*)Wv_w,
                                  (const float4*)Wo_w);

    dim3 pg(HH / 128, (BB * SS) / 128, 3);         // 768 CTAs
    proj_fused<<<pg, 256>>>(Wk_b, Wq_b, Wv_b);

    dim3 fg(SS / 32, BB);                          // (64, 2) = 128 CTAs
    attn_fused<<<fg, 512, fsm>>>();

    dim3 og(HH / 128, (BB * SS) / 64);             // (8, 64)
    outproj_gemm<<<og, 256>>>(Wo_b, out);
}